// round 8
// baseline (speedup 1.0000x reference)
#include <cuda_runtime.h>

// Problem constants
#define NB 2
#define NS 2048
#define NH 16
#define DH 64
#define DM 1024
#define MROWS (NB * NS)   // 4096

// Scratch (device globals — allocation-free)
__device__ float g_q[NB * NH * NS * DH];   // (b,h,s,d) 16MB
__device__ float g_k[NB * NH * NS * DH];
__device__ float g_v[NB * NH * NS * DH];
__device__ float g_att[MROWS * DM];        // (b,s,h*d) 16MB

// XOR swizzle on 4-float groups within a 64-float logical row.
// row: the tile row index (used for the XOR), col: element index 0..63.
__device__ __forceinline__ int swz(int row, int col) {
    return (((col >> 2) ^ (row & 15)) << 2) | (col & 3);
}

// ---------------------------------------------------------------------------
// SGEMM: C(4096x1024) = A(4096x1024) @ W(1024x1024) + bias
// MODE 0: C row-major (r, c). MODE 1: write to (b,h,s,d) scratch layout.
// ---------------------------------------------------------------------------
template <int MODE>
__global__ __launch_bounds__(256) void gemm_bias(const float* __restrict__ A,
                                                 const float* __restrict__ W,
                                                 const float* __restrict__ bias,
                                                 float* __restrict__ C) {
    const int K = DM, N = DM;
    __shared__ float As[16][128];  // A^T tile
    __shared__ float Bs[16][128];

    const int tid  = threadIdx.x;
    const int bm   = blockIdx.y * 128;
    const int bn   = blockIdx.x * 128;
    const int arow = tid >> 2;           // 0..63
    const int acol = (tid & 3) << 2;     // 0,4,8,12
    const int brow = tid >> 5;           // 0..7
    const int bcol = (tid & 31) << 2;    // 0..124
    const int tr   = (tid >> 4) << 2;    // 0..60 (rows tr..tr+3, tr+64..tr+67)
    const int tc   = (tid & 15) << 2;    // 0..60 (cols tc..tc+3, tc+64..tc+67)

    float acc[8][8];
#pragma unroll
    for (int i = 0; i < 8; i++)
#pragma unroll
        for (int j = 0; j < 8; j++) acc[i][j] = 0.f;

    const float* A0 = A + (size_t)(bm + arow) * K;
    const float* A1 = A0 + (size_t)64 * K;

    for (int k0 = 0; k0 < K; k0 += 16) {
        float4 a0 = *(const float4*)(A0 + k0 + acol);
        float4 a1 = *(const float4*)(A1 + k0 + acol);
        As[acol + 0][arow] = a0.x;
        As[acol + 1][arow] = a0.y;
        As[acol + 2][arow] = a0.z;
        As[acol + 3][arow] = a0.w;
        As[acol + 0][arow + 64] = a1.x;
        As[acol + 1][arow + 64] = a1.y;
        As[acol + 2][arow + 64] = a1.z;
        As[acol + 3][arow + 64] = a1.w;
        float4 b0 = *(const float4*)(W + (size_t)(k0 + brow) * N + bn + bcol);
        float4 b1 = *(const float4*)(W + (size_t)(k0 + brow + 8) * N + bn + bcol);
        *(float4*)&Bs[brow][bcol]     = b0;
        *(float4*)&Bs[brow + 8][bcol] = b1;
        __syncthreads();

#pragma unroll
        for (int kk = 0; kk < 16; kk++) {
            float4 x0 = *(float4*)&As[kk][tr];
            float4 x1 = *(float4*)&As[kk][tr + 64];
            float4 y0 = *(float4*)&Bs[kk][tc];
            float4 y1 = *(float4*)&Bs[kk][tc + 64];
            float av[8] = {x0.x, x0.y, x0.z, x0.w, x1.x, x1.y, x1.z, x1.w};
            float bv[8] = {y0.x, y0.y, y0.z, y0.w, y1.x, y1.y, y1.z, y1.w};
#pragma unroll
            for (int i = 0; i < 8; i++)
#pragma unroll
                for (int j = 0; j < 8; j++) acc[i][j] += av[i] * bv[j];
        }
        __syncthreads();
    }

#pragma unroll
    for (int i = 0; i < 8; i++) {
        const int r = bm + tr + ((i < 4) ? i : (60 + i));
#pragma unroll
        for (int jg = 0; jg < 2; jg++) {
            const int c0 = bn + tc + jg * 64;
            float4 v;
            v.x = acc[i][jg * 4 + 0] + bias[c0 + 0];
            v.y = acc[i][jg * 4 + 1] + bias[c0 + 1];
            v.z = acc[i][jg * 4 + 2] + bias[c0 + 2];
            v.w = acc[i][jg * 4 + 3] + bias[c0 + 3];
            if (MODE == 0) {
                *(float4*)&C[(size_t)r * N + c0] = v;
            } else {
                const int b = r >> 11, s = r & (NS - 1);
                const int h = c0 >> 6, d = c0 & 63;
                *(float4*)&C[((size_t)((b << 4) + h) * NS + s) * DH + d] = v;
            }
        }
    }
}

// ---------------------------------------------------------------------------
// Flash attention (fp32). Grid: (NS/64 q-tiles, NB*NH). Block: 256 threads.
// Online softmax over 64-key tiles, additive -1e30 mask bias.
// ---------------------------------------------------------------------------
__global__ __launch_bounds__(256) void attn_kernel(const int* __restrict__ mask) {
    extern __shared__ float sm[];
    float* Qt = sm;            // [dim k][query row], swizzled
    float* Kt = sm + 4096;     // [dim k][key],       swizzled
    float* Vs = sm + 8192;     // [key][dim d],       swizzled
    float* Ps = sm + 12288;    // [query row][key],   plain
    __shared__ float m_s[64], l_s[64], kbias[64];

    const int tid = threadIdx.x;
    const int ty = tid >> 4, tx = tid & 15;
    const int qtile = blockIdx.x;
    const int bh = blockIdx.y;
    const int b = bh >> 4, h = bh & 15;

    const float* qbase = g_q + ((size_t)bh * NS + qtile * 64) * DH;
    const float* kbase = g_k + (size_t)bh * NS * DH;
    const float* vbase = g_v + (size_t)bh * NS * DH;
    const int* mbase = mask + b * NS;

    // Load Q tile (transposed + swizzled), pre-scaled by 1/sqrt(64)
#pragma unroll
    for (int it = 0; it < 16; it++) {
        const int idx = tid + it * 256;
        const int r = idx >> 6, d = idx & 63;
        Qt[d * 64 + swz(d, r)] = qbase[idx] * 0.125f;
    }
    if (tid < 64) { m_s[tid] = -1e30f; l_s[tid] = 0.f; }

    float o[4][4];
#pragma unroll
    for (int i = 0; i < 4; i++)
#pragma unroll
        for (int j = 0; j < 4; j++) o[i][j] = 0.f;
    __syncthreads();

    for (int j0 = 0; j0 < NS; j0 += 64) {
        // Load K (transposed) and V tiles, swizzled
#pragma unroll
        for (int it = 0; it < 16; it++) {
            const int idx = tid + it * 256;
            const int key = idx >> 6, d = idx & 63;
            Kt[d * 64 + swz(d, key)]   = kbase[(size_t)j0 * DH + idx];
            Vs[key * 64 + swz(key, d)] = vbase[(size_t)j0 * DH + idx];
        }
        if (tid < 64) kbias[tid] = (mbase[j0 + tid] != 0) ? -1e30f : 0.f;
        __syncthreads();

        // Scores: sc[i][j] = sum_k Q[qr][k] * K[kr][k]  (Q pre-scaled)
        float sc[4][4];
#pragma unroll
        for (int i = 0; i < 4; i++)
#pragma unroll
            for (int j = 0; j < 4; j++) sc[i][j] = 0.f;

#pragma unroll 16
        for (int kk = 0; kk < 64; kk++) {
            float4 aq = *(float4*)&Qt[kk * 64 + ((ty ^ (kk & 15)) << 2)];
            float4 bk = *(float4*)&Kt[kk * 64 + ((tx ^ (kk & 15)) << 2)];
            float a4[4] = {aq.x, aq.y, aq.z, aq.w};
            float b4[4] = {bk.x, bk.y, bk.z, bk.w};
#pragma unroll
            for (int i = 0; i < 4; i++)
#pragma unroll
                for (int j = 0; j < 4; j++) sc[i][j] += a4[i] * b4[j];
        }

        const float mk[4] = {kbias[tx * 4 + 0], kbias[tx * 4 + 1],
                             kbias[tx * 4 + 2], kbias[tx * 4 + 3]};
#pragma unroll
        for (int i = 0; i < 4; i++)
#pragma unroll
            for (int j = 0; j < 4; j++) sc[i][j] += mk[j];

        // Online softmax per row (16-lane groups live inside one warp)
#pragma unroll
        for (int i = 0; i < 4; i++) {
            const int row = ty * 4 + i;
            float mx = fmaxf(fmaxf(sc[i][0], sc[i][1]), fmaxf(sc[i][2], sc[i][3]));
#pragma unroll
            for (int off = 8; off > 0; off >>= 1)
                mx = fmaxf(mx, __shfl_xor_sync(0xffffffffu, mx, off));
            const float mprev = m_s[row];
            const float nm = fmaxf(mprev, mx);
            const float fac = __expf(mprev - nm);
            float rsum = 0.f;
#pragma unroll
            for (int j = 0; j < 4; j++) {
                const float p = __expf(sc[i][j] - nm);
                sc[i][j] = p;
                rsum += p;
            }
#pragma unroll
            for (int off = 8; off > 0; off >>= 1)
                rsum += __shfl_xor_sync(0xffffffffu, rsum, off);
            if (tx == 0) { m_s[row] = nm; l_s[row] = l_s[row] * fac + rsum; }
            *(float4*)&Ps[row * 64 + tx * 4] =
                make_float4(sc[i][0], sc[i][1], sc[i][2], sc[i][3]);
#pragma unroll
            for (int j = 0; j < 4; j++) o[i][j] *= fac;
        }
        __syncthreads();

        // O += P @ V
#pragma unroll 4
        for (int k4 = 0; k4 < 64; k4 += 4) {
            float4 p4[4], v4[4];
#pragma unroll
            for (int i = 0; i < 4; i++)
                p4[i] = *(float4*)&Ps[(ty * 4 + i) * 64 + k4];
#pragma unroll
            for (int kk = 0; kk < 4; kk++)
                v4[kk] = *(float4*)&Vs[(k4 + kk) * 64 + ((tx ^ ((k4 + kk) & 15)) << 2)];
#pragma unroll
            for (int i = 0; i < 4; i++) {
                float pr[4] = {p4[i].x, p4[i].y, p4[i].z, p4[i].w};
                o[i][0] += pr[0] * v4[0].x + pr[1] * v4[1].x + pr[2] * v4[2].x + pr[3] * v4[3].x;
                o[i][1] += pr[0] * v4[0].y + pr[1] * v4[1].y + pr[2] * v4[2].y + pr[3] * v4[3].y;
                o[i][2] += pr[0] * v4[0].z + pr[1] * v4[1].z + pr[2] * v4[2].z + pr[3] * v4[3].z;
                o[i][3] += pr[0] * v4[0].w + pr[1] * v4[1].w + pr[2] * v4[2].w + pr[3] * v4[3].w;
            }
        }
        __syncthreads();
    }

    // Epilogue: normalize, write to (b, s, h*64+d)
#pragma unroll
    for (int i = 0; i < 4; i++) {
        const int row = ty * 4 + i;
        const float inv = 1.f / l_s[row];
        const int q = qtile * 64 + row;
        float4 v = make_float4(o[i][0] * inv, o[i][1] * inv, o[i][2] * inv, o[i][3] * inv);
        *(float4*)&g_att[((size_t)(b * NS + q)) * DM + h * 64 + tx * 4] = v;
    }
}

// ---------------------------------------------------------------------------
extern "C" void kernel_launch(void* const* d_in, const int* in_sizes, int n_in,
                              void* d_out, int out_size) {
    const float* x    = (const float*)d_in[0];
    const int*   pmask= (const int*)  d_in[1];
    const float* Wq   = (const float*)d_in[2];
    const float* bq   = (const float*)d_in[3];
    const float* Wk   = (const float*)d_in[4];
    const float* bk   = (const float*)d_in[5];
    const float* Wv   = (const float*)d_in[6];
    const float* bv   = (const float*)d_in[7];
    const float* Wo   = (const float*)d_in[8];
    const float* bo   = (const float*)d_in[9];
    float* out = (float*)d_out;

    void *pq, *pk, *pv, *patt;
    cudaGetSymbolAddress(&pq, g_q);
    cudaGetSymbolAddress(&pk, g_k);
    cudaGetSymbolAddress(&pv, g_v);
    cudaGetSymbolAddress(&patt, g_att);

    cudaFuncSetAttribute(attn_kernel, cudaFuncAttributeMaxDynamicSharedMemorySize, 65536);

    dim3 gb(256);
    dim3 gg(DM / 128, MROWS / 128);  // (8, 32)

    gemm_bias<1><<<gg, gb>>>(x, Wq, bq, (float*)pq);
    gemm_bias<1><<<gg, gb>>>(x, Wk, bk, (float*)pk);
    gemm_bias<1><<<gg, gb>>>(x, Wv, bv, (float*)pv);

    dim3 ga(NS / 64, NB * NH);  // (32, 32)
    attn_kernel<<<ga, 256, 65536>>>(pmask);

    gemm_bias<0><<<gg, gb>>>((const float*)patt, Wo, bo, out);
}

// round 9
// speedup vs baseline: 1.0043x; 1.0043x over previous
#include <cuda_runtime.h>

// Problem constants
#define NB 2
#define NS 2048
#define NH 16
#define DH 64
#define DM 1024
#define MROWS (NB * NS)   // 4096

// Scratch (device globals — allocation-free)
__device__ float g_q[NB * NH * NS * DH];   // (b,h,s,d) 16MB
__device__ float g_k[NB * NH * NS * DH];
__device__ float g_v[NB * NH * NS * DH];
__device__ float g_att[MROWS * DM];        // (b,s,h*d) 16MB

// XOR swizzle on 4-float groups within a 64-float logical row.
// row: the tile row index (used for the XOR), col: element index 0..63.
__device__ __forceinline__ int swz(int row, int col) {
    return (((col >> 2) ^ (row & 15)) << 2) | (col & 3);
}

// ---------------------------------------------------------------------------
// SGEMM: C(4096x1024) = A(4096x1024) @ W(1024x1024) + bias
// MODE 0: C row-major (r, c). MODE 1: write to (b,h,s,d) scratch layout.
// ---------------------------------------------------------------------------
template <int MODE>
__global__ __launch_bounds__(256) void gemm_bias(const float* __restrict__ A,
                                                 const float* __restrict__ W,
                                                 const float* __restrict__ bias,
                                                 float* __restrict__ C) {
    const int K = DM, N = DM;
    __shared__ float As[16][128];  // A^T tile
    __shared__ float Bs[16][128];

    const int tid  = threadIdx.x;
    const int bm   = blockIdx.y * 128;
    const int bn   = blockIdx.x * 128;
    const int arow = tid >> 2;           // 0..63
    const int acol = (tid & 3) << 2;     // 0,4,8,12
    const int brow = tid >> 5;           // 0..7
    const int bcol = (tid & 31) << 2;    // 0..124
    const int tr   = (tid >> 4) << 2;    // 0..60 (rows tr..tr+3, tr+64..tr+67)
    const int tc   = (tid & 15) << 2;    // 0..60 (cols tc..tc+3, tc+64..tc+67)

    float acc[8][8];
#pragma unroll
    for (int i = 0; i < 8; i++)
#pragma unroll
        for (int j = 0; j < 8; j++) acc[i][j] = 0.f;

    const float* A0 = A + (size_t)(bm + arow) * K;
    const float* A1 = A0 + (size_t)64 * K;

    for (int k0 = 0; k0 < K; k0 += 16) {
        float4 a0 = *(const float4*)(A0 + k0 + acol);
        float4 a1 = *(const float4*)(A1 + k0 + acol);
        As[acol + 0][arow] = a0.x;
        As[acol + 1][arow] = a0.y;
        As[acol + 2][arow] = a0.z;
        As[acol + 3][arow] = a0.w;
        As[acol + 0][arow + 64] = a1.x;
        As[acol + 1][arow + 64] = a1.y;
        As[acol + 2][arow + 64] = a1.z;
        As[acol + 3][arow + 64] = a1.w;
        float4 b0 = *(const float4*)(W + (size_t)(k0 + brow) * N + bn + bcol);
        float4 b1 = *(const float4*)(W + (size_t)(k0 + brow + 8) * N + bn + bcol);
        *(float4*)&Bs[brow][bcol]     = b0;
        *(float4*)&Bs[brow + 8][bcol] = b1;
        __syncthreads();

#pragma unroll
        for (int kk = 0; kk < 16; kk++) {
            float4 x0 = *(float4*)&As[kk][tr];
            float4 x1 = *(float4*)&As[kk][tr + 64];
            float4 y0 = *(float4*)&Bs[kk][tc];
            float4 y1 = *(float4*)&Bs[kk][tc + 64];
            float av[8] = {x0.x, x0.y, x0.z, x0.w, x1.x, x1.y, x1.z, x1.w};
            float bv[8] = {y0.x, y0.y, y0.z, y0.w, y1.x, y1.y, y1.z, y1.w};
#pragma unroll
            for (int i = 0; i < 8; i++)
#pragma unroll
                for (int j = 0; j < 8; j++) acc[i][j] += av[i] * bv[j];
        }
        __syncthreads();
    }

#pragma unroll
    for (int i = 0; i < 8; i++) {
        const int r = bm + tr + ((i < 4) ? i : (60 + i));
#pragma unroll
        for (int jg = 0; jg < 2; jg++) {
            const int c0 = bn + tc + jg * 64;
            float4 v;
            v.x = acc[i][jg * 4 + 0] + bias[c0 + 0];
            v.y = acc[i][jg * 4 + 1] + bias[c0 + 1];
            v.z = acc[i][jg * 4 + 2] + bias[c0 + 2];
            v.w = acc[i][jg * 4 + 3] + bias[c0 + 3];
            if (MODE == 0) {
                *(float4*)&C[(size_t)r * N + c0] = v;
            } else {
                const int b = r >> 11, s = r & (NS - 1);
                const int h = c0 >> 6, d = c0 & 63;
                *(float4*)&C[((size_t)((b << 4) + h) * NS + s) * DH + d] = v;
            }
        }
    }
}

// ---------------------------------------------------------------------------
// Flash attention (fp32). Grid: (NS/64 q-tiles, NB*NH). Block: 256 threads.
// Online softmax over 64-key tiles, additive -1e30 mask bias.
// ---------------------------------------------------------------------------
__global__ __launch_bounds__(256) void attn_kernel(const int* __restrict__ mask) {
    extern __shared__ float sm[];
    float* Qt = sm;            // [dim k][query row], swizzled
    float* Kt = sm + 4096;     // [dim k][key],       swizzled
    float* Vs = sm + 8192;     // [key][dim d],       swizzled
    float* Ps = sm + 12288;    // [query row][key],   plain
    __shared__ float m_s[64], l_s[64], kbias[64];

    const int tid = threadIdx.x;
    const int ty = tid >> 4, tx = tid & 15;
    const int qtile = blockIdx.x;
    const int bh = blockIdx.y;
    const int b = bh >> 4, h = bh & 15;

    const float* qbase = g_q + ((size_t)bh * NS + qtile * 64) * DH;
    const float* kbase = g_k + (size_t)bh * NS * DH;
    const float* vbase = g_v + (size_t)bh * NS * DH;
    const int* mbase = mask + b * NS;

    // Load Q tile (transposed + swizzled), pre-scaled by 1/sqrt(64)
#pragma unroll
    for (int it = 0; it < 16; it++) {
        const int idx = tid + it * 256;
        const int r = idx >> 6, d = idx & 63;
        Qt[d * 64 + swz(d, r)] = qbase[idx] * 0.125f;
    }
    if (tid < 64) { m_s[tid] = -1e30f; l_s[tid] = 0.f; }

    float o[4][4];
#pragma unroll
    for (int i = 0; i < 4; i++)
#pragma unroll
        for (int j = 0; j < 4; j++) o[i][j] = 0.f;
    __syncthreads();

    for (int j0 = 0; j0 < NS; j0 += 64) {
        // Load K (transposed) and V tiles, swizzled
#pragma unroll
        for (int it = 0; it < 16; it++) {
            const int idx = tid + it * 256;
            const int key = idx >> 6, d = idx & 63;
            Kt[d * 64 + swz(d, key)]   = kbase[(size_t)j0 * DH + idx];
            Vs[key * 64 + swz(key, d)] = vbase[(size_t)j0 * DH + idx];
        }
        if (tid < 64) kbias[tid] = (mbase[j0 + tid] != 0) ? -1e30f : 0.f;
        __syncthreads();

        // Scores: sc[i][j] = sum_k Q[qr][k] * K[kr][k]  (Q pre-scaled)
        float sc[4][4];
#pragma unroll
        for (int i = 0; i < 4; i++)
#pragma unroll
            for (int j = 0; j < 4; j++) sc[i][j] = 0.f;

#pragma unroll 16
        for (int kk = 0; kk < 64; kk++) {
            float4 aq = *(float4*)&Qt[kk * 64 + ((ty ^ (kk & 15)) << 2)];
            float4 bk = *(float4*)&Kt[kk * 64 + ((tx ^ (kk & 15)) << 2)];
            float a4[4] = {aq.x, aq.y, aq.z, aq.w};
            float b4[4] = {bk.x, bk.y, bk.z, bk.w};
#pragma unroll
            for (int i = 0; i < 4; i++)
#pragma unroll
                for (int j = 0; j < 4; j++) sc[i][j] += a4[i] * b4[j];
        }

        const float mk[4] = {kbias[tx * 4 + 0], kbias[tx * 4 + 1],
                             kbias[tx * 4 + 2], kbias[tx * 4 + 3]};
#pragma unroll
        for (int i = 0; i < 4; i++)
#pragma unroll
            for (int j = 0; j < 4; j++) sc[i][j] += mk[j];

        // Online softmax per row (16-lane groups live inside one warp)
#pragma unroll
        for (int i = 0; i < 4; i++) {
            const int row = ty * 4 + i;
            float mx = fmaxf(fmaxf(sc[i][0], sc[i][1]), fmaxf(sc[i][2], sc[i][3]));
#pragma unroll
            for (int off = 8; off > 0; off >>= 1)
                mx = fmaxf(mx, __shfl_xor_sync(0xffffffffu, mx, off));
            const float mprev = m_s[row];
            const float nm = fmaxf(mprev, mx);
            const float fac = __expf(mprev - nm);
            float rsum = 0.f;
#pragma unroll
            for (int j = 0; j < 4; j++) {
                const float p = __expf(sc[i][j] - nm);
                sc[i][j] = p;
                rsum += p;
            }
#pragma unroll
            for (int off = 8; off > 0; off >>= 1)
                rsum += __shfl_xor_sync(0xffffffffu, rsum, off);
            if (tx == 0) { m_s[row] = nm; l_s[row] = l_s[row] * fac + rsum; }
            *(float4*)&Ps[row * 64 + tx * 4] =
                make_float4(sc[i][0], sc[i][1], sc[i][2], sc[i][3]);
#pragma unroll
            for (int j = 0; j < 4; j++) o[i][j] *= fac;
        }
        __syncthreads();

        // O += P @ V
#pragma unroll 4
        for (int k4 = 0; k4 < 64; k4 += 4) {
            float4 p4[4], v4[4];
#pragma unroll
            for (int i = 0; i < 4; i++)
                p4[i] = *(float4*)&Ps[(ty * 4 + i) * 64 + k4];
#pragma unroll
            for (int kk = 0; kk < 4; kk++)
                v4[kk] = *(float4*)&Vs[(k4 + kk) * 64 + ((tx ^ ((k4 + kk) & 15)) << 2)];
#pragma unroll
            for (int i = 0; i < 4; i++) {
                float pr[4] = {p4[i].x, p4[i].y, p4[i].z, p4[i].w};
                o[i][0] += pr[0] * v4[0].x + pr[1] * v4[1].x + pr[2] * v4[2].x + pr[3] * v4[3].x;
                o[i][1] += pr[0] * v4[0].y + pr[1] * v4[1].y + pr[2] * v4[2].y + pr[3] * v4[3].y;
                o[i][2] += pr[0] * v4[0].z + pr[1] * v4[1].z + pr[2] * v4[2].z + pr[3] * v4[3].z;
                o[i][3] += pr[0] * v4[0].w + pr[1] * v4[1].w + pr[2] * v4[2].w + pr[3] * v4[3].w;
            }
        }
        __syncthreads();
    }

    // Epilogue: normalize, write to (b, s, h*64+d)
#pragma unroll
    for (int i = 0; i < 4; i++) {
        const int row = ty * 4 + i;
        const float inv = 1.f / l_s[row];
        const int q = qtile * 64 + row;
        float4 v = make_float4(o[i][0] * inv, o[i][1] * inv, o[i][2] * inv, o[i][3] * inv);
        *(float4*)&g_att[((size_t)(b * NS + q)) * DM + h * 64 + tx * 4] = v;
    }
}

// ---------------------------------------------------------------------------
extern "C" void kernel_launch(void* const* d_in, const int* in_sizes, int n_in,
                              void* d_out, int out_size) {
    const float* x    = (const float*)d_in[0];
    const int*   pmask= (const int*)  d_in[1];
    const float* Wq   = (const float*)d_in[2];
    const float* bq   = (const float*)d_in[3];
    const float* Wk   = (const float*)d_in[4];
    const float* bk   = (const float*)d_in[5];
    const float* Wv   = (const float*)d_in[6];
    const float* bv   = (const float*)d_in[7];
    const float* Wo   = (const float*)d_in[8];
    const float* bo   = (const float*)d_in[9];
    float* out = (float*)d_out;

    void *pq, *pk, *pv, *patt;
    cudaGetSymbolAddress(&pq, g_q);
    cudaGetSymbolAddress(&pk, g_k);
    cudaGetSymbolAddress(&pv, g_v);
    cudaGetSymbolAddress(&patt, g_att);

    cudaFuncSetAttribute(attn_kernel, cudaFuncAttributeMaxDynamicSharedMemorySize, 65536);

    dim3 gb(256);
    dim3 gg(DM / 128, MROWS / 128);  // (8, 32)

    gemm_bias<1><<<gg, gb>>>(x, Wq, bq, (float*)pq);
    gemm_bias<1><<<gg, gb>>>(x, Wk, bk, (float*)pk);
    gemm_bias<1><<<gg, gb>>>(x, Wv, bv, (float*)pv);

    dim3 ga(NS / 64, NB * NH);  // (32, 32)
    attn_kernel<<<ga, 256, 65536>>>(pmask);

    gemm_bias<0><<<gg, gb>>>((const float*)patt, Wo, bo, out);
}